// round 1
// baseline (speedup 1.0000x reference)
#include <cuda_runtime.h>

// Problem: out[100000,128] = x[100000,128] @ (Wc+Wn)[128,128] + b[128]
// (the segment-sum "gamma" in the reference is dead code; edge_index unused)
//
// Inputs (metadata order):
//   d_in[0] = x          float32  [100000, 128]
//   d_in[1] = edge_index int64    [2, 640000]   (UNUSED)
//   d_in[2] = Wc         float32  [128, 128]
//   d_in[3] = Wn         float32  [128, 128]
//   d_in[4] = b          float32  [128]
// out: float32 [100000, 128]

#define D 128

__device__ float g_W[D * D];

__global__ void prep_w_kernel(const float* __restrict__ Wc,
                              const float* __restrict__ Wn) {
    int i = blockIdx.x * blockDim.x + threadIdx.x;
    if (i < D * D) g_W[i] = Wc[i] + Wn[i];
}

// 256 threads, CTA tile: 128 rows x 128 cols, K chunked by 32.
// Each thread computes an 8x8 micro-tile.
__global__ __launch_bounds__(256, 2)
void gemm_bias_kernel(const float* __restrict__ x,
                      const float* __restrict__ bias,
                      float* __restrict__ out,
                      int nrows) {
    __shared__ float xs[32][132];  // [k][row], padded
    __shared__ float ws[32][128];  // [k][col]

    const int tid = threadIdx.x;
    const int tx = tid & 15;        // col group 0..15
    const int ty = tid >> 4;        // row group 0..15
    const int row0 = blockIdx.x * 128;

    float acc[8][8];
#pragma unroll
    for (int i = 0; i < 8; i++)
#pragma unroll
        for (int j = 0; j < 8; j++) acc[i][j] = 0.0f;

    for (int k0 = 0; k0 < D; k0 += 32) {
        // ---- load x chunk (transposed into xs[k][row]) ----
#pragma unroll
        for (int it = 0; it < 4; it++) {
            int r  = (tid >> 3) + 32 * it;   // 0..127 tile row
            int k4 = (tid & 7) * 4;          // k offset 0,4,...,28
            int grow = row0 + r;
            float4 v = make_float4(0.f, 0.f, 0.f, 0.f);
            if (grow < nrows)
                v = *reinterpret_cast<const float4*>(x + (size_t)grow * D + k0 + k4);
            xs[k4 + 0][r] = v.x;
            xs[k4 + 1][r] = v.y;
            xs[k4 + 2][r] = v.z;
            xs[k4 + 3][r] = v.w;
        }
        // ---- load W chunk (contiguous 32x128 floats) ----
        {
            const float4* wsrc = reinterpret_cast<const float4*>(g_W + k0 * D);
            float4* wdst = reinterpret_cast<float4*>(&ws[0][0]);
#pragma unroll
            for (int it = 0; it < 4; it++)
                wdst[tid + 256 * it] = wsrc[tid + 256 * it];
        }
        __syncthreads();

        // ---- compute ----
#pragma unroll 4
        for (int k = 0; k < 32; k++) {
            float4 a0 = *reinterpret_cast<const float4*>(&xs[k][ty * 8]);
            float4 a1 = *reinterpret_cast<const float4*>(&xs[k][ty * 8 + 4]);
            float4 b0 = *reinterpret_cast<const float4*>(&ws[k][tx * 8]);
            float4 b1 = *reinterpret_cast<const float4*>(&ws[k][tx * 8 + 4]);
            float a[8] = {a0.x, a0.y, a0.z, a0.w, a1.x, a1.y, a1.z, a1.w};
            float bb[8] = {b0.x, b0.y, b0.z, b0.w, b1.x, b1.y, b1.z, b1.w};
#pragma unroll
            for (int i = 0; i < 8; i++)
#pragma unroll
                for (int j = 0; j < 8; j++)
                    acc[i][j] = fmaf(a[i], bb[j], acc[i][j]);
        }
        __syncthreads();
    }

    // ---- epilogue: add bias, store ----
    float4 bv0 = *reinterpret_cast<const float4*>(bias + tx * 8);
    float4 bv1 = *reinterpret_cast<const float4*>(bias + tx * 8 + 4);
    float bb[8] = {bv0.x, bv0.y, bv0.z, bv0.w, bv1.x, bv1.y, bv1.z, bv1.w};

#pragma unroll
    for (int i = 0; i < 8; i++) {
        int grow = row0 + ty * 8 + i;
        if (grow < nrows) {
            float4 o0, o1;
            o0.x = acc[i][0] + bb[0];
            o0.y = acc[i][1] + bb[1];
            o0.z = acc[i][2] + bb[2];
            o0.w = acc[i][3] + bb[3];
            o1.x = acc[i][4] + bb[4];
            o1.y = acc[i][5] + bb[5];
            o1.z = acc[i][6] + bb[6];
            o1.w = acc[i][7] + bb[7];
            float* op = out + (size_t)grow * D + tx * 8;
            *reinterpret_cast<float4*>(op) = o0;
            *reinterpret_cast<float4*>(op + 4) = o1;
        }
    }
}

extern "C" void kernel_launch(void* const* d_in, const int* in_sizes, int n_in,
                              void* d_out, int out_size) {
    const float* x    = (const float*)d_in[0];
    // d_in[1] = edge_index (int64) — unused: gamma is dead code in the reference
    const float* Wc   = (const float*)d_in[2];
    const float* Wn   = (const float*)d_in[3];
    const float* bias = (const float*)d_in[4];
    float* out = (float*)d_out;

    const int nrows = in_sizes[0] / D;  // 100000

    prep_w_kernel<<<(D * D + 255) / 256, 256>>>(Wc, Wn);

    int grid = (nrows + 127) / 128;     // 782
    gemm_bias_kernel<<<grid, 256>>>(x, bias, out, nrows);
}

// round 3
// speedup vs baseline: 2.0071x; 2.0071x over previous
#include <cuda_runtime.h>
#include <cstdint>

// out[100000,128] = x[100000,128] @ (Wc+Wn)[128,128] + b[128]
// (gamma/segment-sum in the reference is dead code; edge_index unused)
//
// tf32 mma.sync (m16n8k8) GEMM. CTA: 256 rows x 128 cols, 8 warps of 64x64.
//
// Inputs: d_in[0]=x f32 [100000,128], d_in[1]=edge_index i64 (UNUSED),
//         d_in[2]=Wc f32 [128,128], d_in[3]=Wn f32 [128,128], d_in[4]=b f32 [128]

#define D 128
#define TILE_M 256
#define XS_STRIDE 132   // floats; 132*4B: bank = 4*row_group + t4 -> conflict-free

// W^T, tf32-rounded: g_Wt[n*128 + k] = tf32(Wc[k][n] + Wn[k][n])
__device__ float g_Wt[D * D];

__device__ __forceinline__ float to_tf32(float f) {
    float r;
    asm("cvt.rna.tf32.f32 %0, %1;" : "=f"(r) : "f"(f));
    return r;
}

__global__ void prep_w_kernel(const float* __restrict__ Wc,
                              const float* __restrict__ Wn) {
    int i = blockIdx.x * blockDim.x + threadIdx.x;
    if (i >= D * D) return;
    int n = i >> 7, k = i & 127;
    g_Wt[n * D + k] = to_tf32(Wc[k * D + n] + Wn[k * D + n]);
}

#define MMA_TF32(c, a0, a1, a2, a3, b0, b1)                                   \
    asm volatile(                                                             \
        "mma.sync.aligned.m16n8k8.row.col.f32.tf32.tf32.f32 "                 \
        "{%0,%1,%2,%3}, {%4,%5,%6,%7}, {%8,%9}, {%0,%1,%2,%3};"               \
        : "+f"((c)[0]), "+f"((c)[1]), "+f"((c)[2]), "+f"((c)[3])              \
        : "r"(a0), "r"(a1), "r"(a2), "r"(a3), "r"(b0), "r"(b1))

__global__ __launch_bounds__(256, 1)
void gemm_tf32_kernel(const float* __restrict__ x,
                      const float* __restrict__ bias,
                      float* __restrict__ out, int nrows) {
    extern __shared__ float sm[];
    float* xs = sm;                            // [256][132]
    float* ws = sm + TILE_M * XS_STRIDE;       // [128][132]
    float* bias_s = ws + D * XS_STRIDE;        // [128]

    const int tid = threadIdx.x;
    const int lane = tid & 31;
    const int wid = tid >> 5;
    const int g = lane >> 2;       // 0..7
    const int t4 = lane & 3;       // 0..3
    const int wm = wid >> 1;       // 0..3  (M warp row: 64 rows each)
    const int wn = wid & 1;        // 0..1  (N warp col: 64 cols each)
    const int row0 = blockIdx.x * TILE_M;

    if (tid < D) bias_s[tid] = bias[tid];

    // ---- load W^T tile into smem (stride 132) ----
    {
        const float4* src = (const float4*)g_Wt;
#pragma unroll
        for (int it = 0; it < 16; it++) {
            int idx = tid + 256 * it;          // 0..4095 float4s
            int n = idx >> 5, j = idx & 31;
            *(float4*)(ws + n * XS_STRIDE + 4 * j) = src[idx];
        }
    }
    // ---- load x tile, tf32-round, into smem (stride 132) ----
    {
#pragma unroll
        for (int it = 0; it < 32; it++) {
            int idx = tid + 256 * it;          // 0..8191 float4s
            int r = idx >> 5, j = idx & 31;
            int grow = row0 + r;
            float4 v = make_float4(0.f, 0.f, 0.f, 0.f);
            if (grow < nrows) v = *(const float4*)(x + (size_t)grow * D + 4 * j);
            v.x = to_tf32(v.x); v.y = to_tf32(v.y);
            v.z = to_tf32(v.z); v.w = to_tf32(v.w);
            *(float4*)(xs + r * XS_STRIDE + 4 * j) = v;
        }
    }
    __syncthreads();

    // ---- compute: warp tile 64x64, m16n8k8, 16 k-steps ----
    float acc[4][8][4];
#pragma unroll
    for (int i = 0; i < 4; i++)
#pragma unroll
        for (int j = 0; j < 8; j++)
#pragma unroll
            for (int q = 0; q < 4; q++) acc[i][j][q] = 0.0f;

    const uint32_t* xa = (const uint32_t*)(xs + (wm * 64 + g) * XS_STRIDE + t4);
    const uint32_t* wb = (const uint32_t*)(ws + (wn * 64 + g) * XS_STRIDE + t4);

#pragma unroll 1
    for (int s = 0; s < 16; s++) {
        const int k8 = 8 * s;
        uint32_t a[4][4];
#pragma unroll
        for (int i = 0; i < 4; i++) {
            a[i][0] = xa[i * 16 * XS_STRIDE + k8];
            a[i][1] = xa[i * 16 * XS_STRIDE + 8 * XS_STRIDE + k8];
            a[i][2] = xa[i * 16 * XS_STRIDE + k8 + 4];
            a[i][3] = xa[i * 16 * XS_STRIDE + 8 * XS_STRIDE + k8 + 4];
        }
        uint32_t b[8][2];
#pragma unroll
        for (int j = 0; j < 8; j++) {
            b[j][0] = wb[j * 8 * XS_STRIDE + k8];
            b[j][1] = wb[j * 8 * XS_STRIDE + k8 + 4];
        }
#pragma unroll
        for (int i = 0; i < 4; i++)
#pragma unroll
            for (int j = 0; j < 8; j++)
                MMA_TF32(acc[i][j], a[i][0], a[i][1], a[i][2], a[i][3],
                         b[j][0], b[j][1]);
    }

    // ---- epilogue: bias + store directly from accumulators ----
    // m16n8 acc layout: c0,c1 at (row=g, col=2*t4, 2*t4+1); c2,c3 at row=g+8.
#pragma unroll
    for (int j = 0; j < 8; j++) {
        int col = wn * 64 + 8 * j + 2 * t4;
        float b0 = bias_s[col], b1 = bias_s[col + 1];
#pragma unroll
        for (int i = 0; i < 4; i++) {
            int r_lo = row0 + wm * 64 + 16 * i + g;
            int r_hi = r_lo + 8;
            if (r_lo < nrows) {
                float2 v = make_float2(acc[i][j][0] + b0, acc[i][j][1] + b1);
                *(float2*)(out + (size_t)r_lo * D + col) = v;
            }
            if (r_hi < nrows) {
                float2 v = make_float2(acc[i][j][2] + b0, acc[i][j][3] + b1);
                *(float2*)(out + (size_t)r_hi * D + col) = v;
            }
        }
    }
}

extern "C" void kernel_launch(void* const* d_in, const int* in_sizes, int n_in,
                              void* d_out, int out_size) {
    const float* x    = (const float*)d_in[0];
    const float* Wc   = (const float*)d_in[2];
    const float* Wn   = (const float*)d_in[3];
    const float* bias = (const float*)d_in[4];
    float* out = (float*)d_out;

    const int nrows = in_sizes[0] / D;  // 100000

    prep_w_kernel<<<(D * D + 255) / 256, 256>>>(Wc, Wn);

    const int smem_bytes = (TILE_M * XS_STRIDE + D * XS_STRIDE + D) * 4;
    cudaFuncSetAttribute(gemm_tf32_kernel,
                         cudaFuncAttributeMaxDynamicSharedMemorySize, smem_bytes);

    int grid = (nrows + TILE_M - 1) / TILE_M;  // 391
    gemm_tf32_kernel<<<grid, 256, smem_bytes>>>(x, bias, out, nrows);
}